// round 1
// baseline (speedup 1.0000x reference)
#include <cuda_runtime.h>
#include <math.h>

// Problem constants
namespace {
constexpr int kB = 256;   // batch
constexpr int kT = 256;   // timesteps
constexpr int kI = 512;   // input dim
constexpr int kH = 1024;  // hidden dim

constexpr int TM = 32;    // rows (batches) per CTA tile
constexpr int TN = 64;    // cols (hidden units) per CTA tile
constexpr int TK = 16;    // K chunk
}

// Scratch (no allocations allowed in kernel_launch)
__device__ float g_h[2][kB * kH];   // ping-pong hidden state
__device__ int g_order[kB];         // batches sorted by length desc
__device__ int g_count[kT];         // c_t = #{b : L_b > t}

// ---------------------------------------------------------------------------
__global__ void init_kernel() {
  int i = blockIdx.x * blockDim.x + threadIdx.x;
  if (i < kB * kH) g_h[0][i] = 0.0f;
}

// Counting sort of batches by seq_length (descending) + active-count table.
// Handles seq_lengths stored as int64 OR int32 (JAX x64-off silently downcasts).
__global__ void sort_kernel(const void* __restrict__ seq_raw) {
  __shared__ int hist[kT + 1];
  __shared__ int off[kT + 1];
  __shared__ int is64;
  int tid = threadIdx.x;  // 256 threads == kB == kT
  hist[tid] = 0;
  if (tid == 0) {
    hist[kT] = 0;
    // If int64: little-endian high words of small values are all zero.
    const int* v = (const int*)seq_raw;
    int f = 1;
    for (int i = 0; i < 32; ++i) {
      if (v[2 * i + 1] != 0) { f = 0; break; }
    }
    is64 = f;
  }
  __syncthreads();
  long long Lv = is64 ? ((const long long*)seq_raw)[tid]
                      : (long long)((const int*)seq_raw)[tid];
  int L = (int)Lv;
  if (L < 0) L = 0;
  if (L > kT) L = kT;
  atomicAdd(&hist[L], 1);
  __syncthreads();
  if (tid == 0) {
    int run = 0;
    for (int t = kT - 1; t >= 0; --t) {
      run += hist[t + 1];
      g_count[t] = run;   // #{L > t}
      off[t] = run;       // start position of the L == t group
    }
    off[kT] = 0;          // L == kT group (shouldn't occur) goes first
  }
  __syncthreads();
  int pos = atomicAdd(&off[L], 1);
  g_order[pos] = tid;
}

// ---------------------------------------------------------------------------
// One recurrence step t:
//   rows [0, c_t) of the sorted order:  h_out = tanh(x_t@Wx_t^T + h_in@Wh_t^T + b_t)
//   rows [c_t, B):                      h_out = h_in   (frozen)
__global__ __launch_bounds__(256) void step_kernel(
    int t, int pp, const float* __restrict__ x, const float* __restrict__ Wx,
    const float* __restrict__ Wh, const float* __restrict__ bias) {
  __shared__ float As[TK][TM + 4];  // stride 36 (even -> aligned float2 reads)
  __shared__ float Bs[TK][TN + 4];  // stride 68 (mult of 4 -> aligned float4)
  __shared__ int rowB[TM];

  const float* __restrict__ hIn = g_h[pp];
  float* __restrict__ hOut = g_h[pp ^ 1];

  const int c = g_count[t];
  const int rowBase = blockIdx.x * TM;
  const int colBase = blockIdx.y * TN;
  const int tid = threadIdx.x;

  if (tid < TM) rowB[tid] = g_order[rowBase + tid];
  __syncthreads();

  if (rowBase >= c) {
    // Fully inactive tile: carry state forward.
    for (int i = tid; i < TM * TN; i += 256) {
      int r = i >> 6;           // / TN
      int n = i & (TN - 1);
      size_t idx = (size_t)rowB[r] * kH + colBase + n;
      hOut[idx] = hIn[idx];
    }
    return;
  }

  const int tx = tid & 15;   // 16 col groups of 4
  const int ty = tid >> 4;   // 16 row groups of 2
  const int lkA = tid & 7;   // A loader: k-pair 0..7
  const int lmA = tid >> 3;  // A loader: row 0..31
  const int lkB = tid & 3;   // B loader: k-quad 0..3
  const int lnB = tid >> 2;  // B loader: col 0..63

  const int bA = rowB[lmA];

  float acc[2][4];
#pragma unroll
  for (int i = 0; i < 2; ++i)
#pragma unroll
    for (int j = 0; j < 4; ++j) acc[i][j] = 0.0f;

  // ---- Phase 1: x_t @ Wx_t^T  (K = kI) ----
  {
    const float* __restrict__ arow = x + (size_t)bA * kT * kI + (size_t)t * kI;
    const float* __restrict__ wrow =
        Wx + (size_t)t * kH * kI + (size_t)(colBase + lnB) * kI;
    for (int k0 = 0; k0 < kI; k0 += TK) {
      float2 av = *(const float2*)(arow + k0 + lkA * 2);
      As[lkA * 2 + 0][lmA] = av.x;
      As[lkA * 2 + 1][lmA] = av.y;
      float4 bv = *(const float4*)(wrow + k0 + lkB * 4);
      Bs[lkB * 4 + 0][lnB] = bv.x;
      Bs[lkB * 4 + 1][lnB] = bv.y;
      Bs[lkB * 4 + 2][lnB] = bv.z;
      Bs[lkB * 4 + 3][lnB] = bv.w;
      __syncthreads();
#pragma unroll
      for (int kk = 0; kk < TK; ++kk) {
        float2 a = *(const float2*)&As[kk][ty * 2];
        float4 bb = *(const float4*)&Bs[kk][tx * 4];
        acc[0][0] += a.x * bb.x; acc[0][1] += a.x * bb.y;
        acc[0][2] += a.x * bb.z; acc[0][3] += a.x * bb.w;
        acc[1][0] += a.y * bb.x; acc[1][1] += a.y * bb.y;
        acc[1][2] += a.y * bb.z; acc[1][3] += a.y * bb.w;
      }
      __syncthreads();
    }
  }

  // ---- Phase 2: h @ Wh_t^T  (K = kH) ----
  {
    const float* __restrict__ arow = hIn + (size_t)bA * kH;
    const float* __restrict__ wrow =
        Wh + (size_t)t * kH * kH + (size_t)(colBase + lnB) * kH;
    for (int k0 = 0; k0 < kH; k0 += TK) {
      float2 av = *(const float2*)(arow + k0 + lkA * 2);
      As[lkA * 2 + 0][lmA] = av.x;
      As[lkA * 2 + 1][lmA] = av.y;
      float4 bv = *(const float4*)(wrow + k0 + lkB * 4);
      Bs[lkB * 4 + 0][lnB] = bv.x;
      Bs[lkB * 4 + 1][lnB] = bv.y;
      Bs[lkB * 4 + 2][lnB] = bv.z;
      Bs[lkB * 4 + 3][lnB] = bv.w;
      __syncthreads();
#pragma unroll
      for (int kk = 0; kk < TK; ++kk) {
        float2 a = *(const float2*)&As[kk][ty * 2];
        float4 bb = *(const float4*)&Bs[kk][tx * 4];
        acc[0][0] += a.x * bb.x; acc[0][1] += a.x * bb.y;
        acc[0][2] += a.x * bb.z; acc[0][3] += a.x * bb.w;
        acc[1][0] += a.y * bb.x; acc[1][1] += a.y * bb.y;
        acc[1][2] += a.y * bb.z; acc[1][3] += a.y * bb.w;
      }
      __syncthreads();
    }
  }

  // ---- Epilogue: bias + tanh for active rows, carry for frozen rows ----
  const float* __restrict__ brow = bias + (size_t)t * kH + colBase;
#pragma unroll
  for (int i = 0; i < 2; ++i) {
    int m = ty * 2 + i;
    int b = rowB[m];
    bool active = (rowBase + m) < c;
#pragma unroll
    for (int j = 0; j < 4; ++j) {
      int n = tx * 4 + j;
      size_t idx = (size_t)b * kH + colBase + n;
      hOut[idx] = active ? tanhf(acc[i][j] + brow[n]) : hIn[idx];
    }
  }
}

// ---------------------------------------------------------------------------
// out[b] = h_final[b] . W_out + b_out  (O == 1)
__global__ void out_kernel(const float* __restrict__ Wout,
                           const float* __restrict__ bout,
                           float* __restrict__ out) {
  int b = blockIdx.x;
  const float* h = g_h[0] + (size_t)b * kH;  // T even -> final state in buf 0
  float s = 0.0f;
  for (int i = threadIdx.x; i < kH; i += blockDim.x) s += h[i] * Wout[i];
#pragma unroll
  for (int o = 16; o > 0; o >>= 1) s += __shfl_down_sync(0xffffffffu, s, o);
  __shared__ float red[8];
  if ((threadIdx.x & 31) == 0) red[threadIdx.x >> 5] = s;
  __syncthreads();
  if (threadIdx.x == 0) {
    float tot = 0.0f;
    for (int w = 0; w < 8; ++w) tot += red[w];
    out[b] = tot + bout[0];
  }
}

// ---------------------------------------------------------------------------
extern "C" void kernel_launch(void* const* d_in, const int* in_sizes, int n_in,
                              void* d_out, int out_size) {
  const float* x = (const float*)d_in[0];
  const void* seq = d_in[1];
  const float* Wx = (const float*)d_in[2];
  const float* Wh = (const float*)d_in[3];
  const float* bias = (const float*)d_in[4];
  const float* Wout = (const float*)d_in[5];
  const float* bout = (const float*)d_in[6];
  float* out = (float*)d_out;

  init_kernel<<<(kB * kH + 255) / 256, 256>>>();
  sort_kernel<<<1, kB>>>(seq);

  dim3 grid(kB / TM, kH / TN);
  for (int t = 0; t < kT; ++t) {
    step_kernel<<<grid, 256>>>(t, t & 1, x, Wx, Wh, bias);
  }
  out_kernel<<<kB, 256>>>(Wout, bout, out);
}

// round 2
// speedup vs baseline: 2.0791x; 2.0791x over previous
#include <cuda_runtime.h>
#include <math.h>

namespace {
constexpr int kB = 256;   // batch
constexpr int kT = 256;   // timesteps
constexpr int kI = 512;   // input dim
constexpr int kH = 1024;  // hidden dim
}

// ---------------- packed f32x2 helpers (SASS FFMA2 path) --------------------
__device__ __forceinline__ unsigned long long pack2(float x, float y) {
  unsigned long long r;
  asm("mov.b64 %0, {%1, %2};" : "=l"(r) : "f"(x), "f"(y));
  return r;
}
__device__ __forceinline__ void fma2(unsigned long long& d, unsigned long long a,
                                     unsigned long long b) {
  asm("fma.rn.f32x2 %0, %1, %2, %0;" : "+l"(d) : "l"(a), "l"(b));
}
__device__ __forceinline__ void add2(unsigned long long& d, unsigned long long a) {
  asm("add.rn.f32x2 %0, %1, %0;" : "+l"(d) : "l"(a));
}
__device__ __forceinline__ float2 unpack2(unsigned long long v) {
  float2 r;
  asm("mov.b64 {%0, %1}, %2;" : "=f"(r.x), "=f"(r.y) : "l"(v));
  return r;
}

// ---------------- device scratch (no allocations allowed) -------------------
__device__ float g_h[2][kB * kH];                 // ping-pong hidden state (by sorted pos)
__device__ float g_pre[(size_t)kT * kB * kH];     // pre[t][pos][n] = x@Wx^T + b   (268 MB)
__device__ int g_order[kB];                       // sorted pos -> original batch idx
__device__ int g_lens[kB];                        // length per sorted pos
__device__ int g_count[kT];                       // c_t = #{L > t}, non-increasing

// ---------------------------------------------------------------------------
__global__ void init_kernel() {
  int i = blockIdx.x * blockDim.x + threadIdx.x;
  if (i < kB * kH) { g_h[0][i] = 0.0f; g_h[1][i] = 0.0f; }
}

// Counting sort of batches by seq_length (descending). Handles int64 or int32.
__global__ void sort_kernel(const void* __restrict__ seq_raw) {
  __shared__ int hist[kT + 2];
  __shared__ int off[kT + 2];
  __shared__ int is64;
  int tid = threadIdx.x;  // 256 threads
  hist[tid] = 0;
  if (tid == 0) {
    hist[kT] = 0; hist[kT + 1] = 0;
    const int* v = (const int*)seq_raw;
    int f = 1;
    for (int i = 0; i < 32; ++i)
      if (v[2 * i + 1] != 0) { f = 0; break; }
    is64 = f;
  }
  __syncthreads();
  long long Lv = is64 ? ((const long long*)seq_raw)[tid]
                      : (long long)((const int*)seq_raw)[tid];
  int L = (int)Lv;
  if (L < 0) L = 0;
  if (L > kT) L = kT;
  atomicAdd(&hist[L], 1);
  __syncthreads();
  if (tid == 0) {
    int run = 0;
    for (int t = kT; t >= 0; --t) {
      run += hist[t + 1];
      if (t < kT) g_count[t] = run;  // #{L > t}
      off[t] = run;                  // start of the L == t group
    }
    off[kT + 1] = 0;
  }
  __syncthreads();
  int pos = atomicAdd(&off[L], 1);
  g_order[pos] = tid;
  g_lens[pos] = L;
}

// ---------------------------------------------------------------------------
// Phase A (fully parallel): pre[t][pos][n] = x[order[pos], t] @ Wx_t^T + b_t[n]
// Tile 64x64, K=512, 256 threads, 4x4 microtile in f32x2 pairs, double-buffered.
__global__ __launch_bounds__(256) void preA_kernel(const float* __restrict__ x,
                                                   const float* __restrict__ Wx,
                                                   const float* __restrict__ bias) {
  __shared__ float As[2][16][68];
  __shared__ float Bs[2][16][68];
  __shared__ int rowB[64];

  const int t = blockIdx.z;
  const int rowBase = blockIdx.x * 64;
  const int colBase = blockIdx.y * 64;
  const int c = g_count[t];
  if (rowBase >= c) return;  // tile fully masked: pre never read

  const int tid = threadIdx.x;
  if (tid < 64) rowB[tid] = g_order[rowBase + tid];
  __syncthreads();

  // loader indices
  const int lr = tid >> 2;       // 0..63
  const int lk = (tid & 3) * 4;  // k offset 0,4,8,12
  const float* __restrict__ arow = x + ((size_t)rowB[lr] * kT + t) * kI;
  const float* __restrict__ brow = Wx + ((size_t)t * kH + colBase + lr) * kI;

  // compute indices
  const int tx = tid & 15;   // col group (4 cols)
  const int ty = tid >> 4;   // row group (4 rows)

  unsigned long long acc[4][2];
#pragma unroll
  for (int m = 0; m < 4; ++m) { acc[m][0] = 0ull; acc[m][1] = 0ull; }

  // preload chunk 0
  float4 av = *(const float4*)(arow + lk);
  float4 bv = *(const float4*)(brow + lk);
  As[0][lk + 0][lr] = av.x; As[0][lk + 1][lr] = av.y;
  As[0][lk + 2][lr] = av.z; As[0][lk + 3][lr] = av.w;
  Bs[0][lk + 0][lr] = bv.x; Bs[0][lk + 1][lr] = bv.y;
  Bs[0][lk + 2][lr] = bv.z; Bs[0][lk + 3][lr] = bv.w;
  __syncthreads();

  const int nChunks = kI / 16;  // 32
  for (int ci = 0; ci < nChunks; ++ci) {
    int cur = ci & 1;
    if (ci + 1 < nChunks) {
      int k0 = (ci + 1) * 16;
      av = *(const float4*)(arow + k0 + lk);
      bv = *(const float4*)(brow + k0 + lk);
    }
#pragma unroll
    for (int kk = 0; kk < 16; ++kk) {
      float4 a4 = *(const float4*)&As[cur][kk][ty * 4];
      unsigned long long b0 = *(const unsigned long long*)&Bs[cur][kk][tx * 4];
      unsigned long long b1 = *(const unsigned long long*)&Bs[cur][kk][tx * 4 + 2];
      unsigned long long a0 = pack2(a4.x, a4.x);
      unsigned long long a1 = pack2(a4.y, a4.y);
      unsigned long long a2 = pack2(a4.z, a4.z);
      unsigned long long a3 = pack2(a4.w, a4.w);
      fma2(acc[0][0], a0, b0); fma2(acc[0][1], a0, b1);
      fma2(acc[1][0], a1, b0); fma2(acc[1][1], a1, b1);
      fma2(acc[2][0], a2, b0); fma2(acc[2][1], a2, b1);
      fma2(acc[3][0], a3, b0); fma2(acc[3][1], a3, b1);
    }
    if (ci + 1 < nChunks) {
      int nxt = cur ^ 1;
      As[nxt][lk + 0][lr] = av.x; As[nxt][lk + 1][lr] = av.y;
      As[nxt][lk + 2][lr] = av.z; As[nxt][lk + 3][lr] = av.w;
      Bs[nxt][lk + 0][lr] = bv.x; Bs[nxt][lk + 1][lr] = bv.y;
      Bs[nxt][lk + 2][lr] = bv.z; Bs[nxt][lk + 3][lr] = bv.w;
    }
    __syncthreads();
  }

  // epilogue: + bias, write pre[t][row][col]
  const float* __restrict__ bptr = bias + (size_t)t * kH + colBase + tx * 4;
  float4 b4 = *(const float4*)bptr;
#pragma unroll
  for (int m = 0; m < 4; ++m) {
    int row = rowBase + ty * 4 + m;
    float2 lo = unpack2(acc[m][0]);
    float2 hi = unpack2(acc[m][1]);
    float4 o;
    o.x = lo.x + b4.x; o.y = lo.y + b4.y; o.z = hi.x + b4.z; o.w = hi.y + b4.w;
    *(float4*)(g_pre + ((size_t)t * kB + row) * kH + colBase + tx * 4) = o;
  }
}

// ---------------------------------------------------------------------------
// Phase B step t (serial): rows pos < c_t: h_out = tanh(pre[t][pos] + h_in[pos] @ Wh_t^T)
// Tile 16x64 over (pos, n). 256 threads = 2 K-groups of 128 (K=512 each).
__global__ __launch_bounds__(256) void step_kernel(int t, const float* __restrict__ Wh) {
  __shared__ float As[2][2][16][20];   // [grp][buf][k][m]
  __shared__ float Bs[2][2][16][68];   // [grp][buf][k][n]
  __shared__ float Red[16][64];

  const int c = g_count[t];
  const int rowBase = blockIdx.x * 16;
  if (rowBase >= c) return;
  const int colBase = blockIdx.y * 64;

  const int pp = t & 1;
  const float* __restrict__ hIn = g_h[pp];
  float* __restrict__ hOut = g_h[pp ^ 1];

  const int tid = threadIdx.x;
  const int g = tid >> 7;       // k-group 0/1
  const int ltid = tid & 127;
  const int kStart = g * 512;

  // loader indices
  const int lrA = ltid >> 3;          // 0..15 (row)
  const int lkA = (ltid & 7) * 2;     // k offset (float2)
  const int lnB = ltid >> 1;          // 0..63 (col)
  const int lkB = (ltid & 1) * 8;     // k offset (2x float4)

  const float* __restrict__ arow = hIn + (size_t)(rowBase + lrA) * kH + kStart;
  const float* __restrict__ brow =
      Wh + ((size_t)t * kH + colBase + lnB) * kH + kStart;

  // compute indices
  const int tx = ltid & 15;   // 4 cols
  const int ty = ltid >> 4;   // 0..7 -> 2 rows

  unsigned long long acc[2][2];
  acc[0][0] = acc[0][1] = acc[1][0] = acc[1][1] = 0ull;

  // preload chunk 0
  float2 av = *(const float2*)(arow + lkA);
  float4 bv0 = *(const float4*)(brow + lkB);
  float4 bv1 = *(const float4*)(brow + lkB + 4);
  As[g][0][lkA + 0][lrA] = av.x;
  As[g][0][lkA + 1][lrA] = av.y;
  Bs[g][0][lkB + 0][lnB] = bv0.x; Bs[g][0][lkB + 1][lnB] = bv0.y;
  Bs[g][0][lkB + 2][lnB] = bv0.z; Bs[g][0][lkB + 3][lnB] = bv0.w;
  Bs[g][0][lkB + 4][lnB] = bv1.x; Bs[g][0][lkB + 5][lnB] = bv1.y;
  Bs[g][0][lkB + 6][lnB] = bv1.z; Bs[g][0][lkB + 7][lnB] = bv1.w;
  __syncthreads();

  const int nChunks = 512 / 16;  // 32 per group
  for (int ci = 0; ci < nChunks; ++ci) {
    int cur = ci & 1;
    if (ci + 1 < nChunks) {
      int k0 = (ci + 1) * 16;
      av = *(const float2*)(arow + k0 + lkA);
      bv0 = *(const float4*)(brow + k0 + lkB);
      bv1 = *(const float4*)(brow + k0 + lkB + 4);
    }
#pragma unroll
    for (int kk = 0; kk < 16; ++kk) {
      float2 a2 = *(const float2*)&As[g][cur][kk][ty * 2];
      unsigned long long b0 = *(const unsigned long long*)&Bs[g][cur][kk][tx * 4];
      unsigned long long b1 = *(const unsigned long long*)&Bs[g][cur][kk][tx * 4 + 2];
      unsigned long long a0 = pack2(a2.x, a2.x);
      unsigned long long a1 = pack2(a2.y, a2.y);
      fma2(acc[0][0], a0, b0); fma2(acc[0][1], a0, b1);
      fma2(acc[1][0], a1, b0); fma2(acc[1][1], a1, b1);
    }
    if (ci + 1 < nChunks) {
      int nxt = cur ^ 1;
      As[g][nxt][lkA + 0][lrA] = av.x;
      As[g][nxt][lkA + 1][lrA] = av.y;
      Bs[g][nxt][lkB + 0][lnB] = bv0.x; Bs[g][nxt][lkB + 1][lnB] = bv0.y;
      Bs[g][nxt][lkB + 2][lnB] = bv0.z; Bs[g][nxt][lkB + 3][lnB] = bv0.w;
      Bs[g][nxt][lkB + 4][lnB] = bv1.x; Bs[g][nxt][lkB + 5][lnB] = bv1.y;
      Bs[g][nxt][lkB + 6][lnB] = bv1.z; Bs[g][nxt][lkB + 7][lnB] = bv1.w;
    }
    __syncthreads();
  }

  // group 1 deposits partials; group 0 reduces + epilogue
  if (g == 1) {
#pragma unroll
    for (int m = 0; m < 2; ++m) {
      *(unsigned long long*)&Red[ty * 2 + m][tx * 4 + 0] = acc[m][0];
      *(unsigned long long*)&Red[ty * 2 + m][tx * 4 + 2] = acc[m][1];
    }
  }
  __syncthreads();
  if (g == 0) {
#pragma unroll
    for (int m = 0; m < 2; ++m) {
      add2(acc[m][0], *(const unsigned long long*)&Red[ty * 2 + m][tx * 4 + 0]);
      add2(acc[m][1], *(const unsigned long long*)&Red[ty * 2 + m][tx * 4 + 2]);
      int pos = rowBase + ty * 2 + m;
      if (pos < c) {
        const float* pr = g_pre + ((size_t)t * kB + pos) * kH + colBase + tx * 4;
        float4 p4 = *(const float4*)pr;
        float2 lo = unpack2(acc[m][0]);
        float2 hi = unpack2(acc[m][1]);
        float4 o;
        o.x = tanhf(lo.x + p4.x);
        o.y = tanhf(lo.y + p4.y);
        o.z = tanhf(hi.x + p4.z);
        o.w = tanhf(hi.y + p4.w);
        *(float4*)(hOut + (size_t)pos * kH + colBase + tx * 4) = o;
      }
    }
  }
}

// ---------------------------------------------------------------------------
// out[order[pos]] = h_final[pos] . W_out + b_out  (final h lives in buffer L&1)
__global__ void out_kernel(const float* __restrict__ Wout,
                           const float* __restrict__ bout,
                           float* __restrict__ out) {
  int pos = blockIdx.x;
  int L = g_lens[pos];
  const float* h = g_h[L & 1] + (size_t)pos * kH;
  float s = 0.0f;
  for (int i = threadIdx.x; i < kH; i += blockDim.x) s += h[i] * Wout[i];
#pragma unroll
  for (int o = 16; o > 0; o >>= 1) s += __shfl_down_sync(0xffffffffu, s, o);
  __shared__ float red[4];
  if ((threadIdx.x & 31) == 0) red[threadIdx.x >> 5] = s;
  __syncthreads();
  if (threadIdx.x == 0) {
    float tot = red[0] + red[1] + red[2] + red[3];
    out[g_order[pos]] = tot + bout[0];
  }
}

// ---------------------------------------------------------------------------
extern "C" void kernel_launch(void* const* d_in, const int* in_sizes, int n_in,
                              void* d_out, int out_size) {
  const float* x = (const float*)d_in[0];
  const void* seq = d_in[1];
  const float* Wx = (const float*)d_in[2];
  const float* Wh = (const float*)d_in[3];
  const float* bias = (const float*)d_in[4];
  const float* Wout = (const float*)d_in[5];
  const float* bout = (const float*)d_in[6];
  float* out = (float*)d_out;

  init_kernel<<<(kB * kH + 255) / 256, 256>>>();
  sort_kernel<<<1, kB>>>(seq);

  // Phase A: all (t, row-tile, col-tile) GEMMs in one launch
  preA_kernel<<<dim3(kB / 64, kH / 64, kT), 256>>>(x, Wx, bias);

  // Phase B: sequential recurrence
  for (int t = 0; t < kT; ++t) {
    step_kernel<<<dim3(16, 16), 256>>>(t, Wh);
  }
  out_kernel<<<kB, 128>>>(Wout, bout, out);
}

// round 7
// speedup vs baseline: 2.0917x; 1.0060x over previous
#include <cuda_runtime.h>
#include <math.h>

namespace {
constexpr int kB = 256;   // batch
constexpr int kT = 256;   // timesteps
constexpr int kI = 512;   // input dim
constexpr int kH = 1024;  // hidden dim
}

// ---------------- packed f32x2 helpers (SASS FFMA2 path) --------------------
__device__ __forceinline__ unsigned long long pack2(float x, float y) {
  unsigned long long r;
  asm("mov.b64 %0, {%1, %2};" : "=l"(r) : "f"(x), "f"(y));
  return r;
}
__device__ __forceinline__ void fma2(unsigned long long& d, unsigned long long a,
                                     unsigned long long b) {
  asm("fma.rn.f32x2 %0, %1, %2, %0;" : "+l"(d) : "l"(a), "l"(b));
}
__device__ __forceinline__ void add2(unsigned long long& d, unsigned long long a) {
  asm("add.rn.f32x2 %0, %1, %0;" : "+l"(d) : "l"(a));
}
__device__ __forceinline__ float2 unpack2(unsigned long long v) {
  float2 r;
  asm("mov.b64 {%0, %1}, %2;" : "=f"(r.x), "=f"(r.y) : "l"(v));
  return r;
}
__device__ __forceinline__ void pf_l2(const float* p) {
  asm volatile("prefetch.global.L2 [%0];" ::"l"(p));
}

// ---------------- device scratch (no allocations allowed) -------------------
__device__ float g_h[2][kB * kH];               // ping-pong hidden state (sorted pos)
__device__ float g_pre[(size_t)kT * kB * kH];   // pre[t][pos][n] = x@Wx^T + b
__device__ int g_order[kB];                     // sorted pos -> original batch idx
__device__ int g_lens[kB];                      // length per sorted pos
__device__ int g_count[kT];                     // c_t = #{L > t}, non-increasing

// ---------------------------------------------------------------------------
__global__ void init_kernel() {
  int i = blockIdx.x * blockDim.x + threadIdx.x;
  if (i < kB * kH) { g_h[0][i] = 0.0f; g_h[1][i] = 0.0f; }
}

// Counting sort of batches by seq_length (descending). Handles int64 or int32.
__global__ void sort_kernel(const void* __restrict__ seq_raw) {
  __shared__ int hist[kT + 2];
  __shared__ int off[kT + 2];
  __shared__ int is64;
  int tid = threadIdx.x;  // 256 threads
  hist[tid] = 0;
  if (tid == 0) {
    hist[kT] = 0; hist[kT + 1] = 0;
    const int* v = (const int*)seq_raw;
    int f = 1;
    for (int i = 0; i < 32; ++i)
      if (v[2 * i + 1] != 0) { f = 0; break; }
    is64 = f;
  }
  __syncthreads();
  long long Lv = is64 ? ((const long long*)seq_raw)[tid]
                      : (long long)((const int*)seq_raw)[tid];
  int L = (int)Lv;
  if (L < 0) L = 0;
  if (L > kT) L = kT;
  atomicAdd(&hist[L], 1);
  __syncthreads();
  if (tid == 0) {
    int run = 0;
    for (int t = kT; t >= 0; --t) {
      run += hist[t + 1];
      if (t < kT) g_count[t] = run;  // #{L > t}
      off[t] = run;                  // start of the L == t group
    }
    off[kT + 1] = 0;
  }
  __syncthreads();
  int pos = atomicAdd(&off[L], 1);
  g_order[pos] = tid;
  g_lens[pos] = L;
}

// ---------------------------------------------------------------------------
// Phase A (fully parallel): pre[t][pos][n] = x[order[pos], t] @ Wx_t^T + b_t[n]
__global__ __launch_bounds__(256) void preA_kernel(const float* __restrict__ x,
                                                   const float* __restrict__ Wx,
                                                   const float* __restrict__ bias) {
  __shared__ float As[2][16][68];
  __shared__ float Bs[2][16][68];
  __shared__ int rowB[64];

  const int t = blockIdx.z;
  const int rowBase = blockIdx.x * 64;
  const int colBase = blockIdx.y * 64;
  const int c = g_count[t];
  if (rowBase >= c) return;  // tile fully masked: pre never read

  const int tid = threadIdx.x;
  if (tid < 64) rowB[tid] = g_order[rowBase + tid];
  __syncthreads();

  const int lr = tid >> 2;       // 0..63
  const int lk = (tid & 3) * 4;  // k offset 0,4,8,12
  const float* __restrict__ arow = x + ((size_t)rowB[lr] * kT + t) * kI;
  const float* __restrict__ brow = Wx + ((size_t)t * kH + colBase + lr) * kI;

  const int tx = tid & 15;
  const int ty = tid >> 4;

  unsigned long long acc[4][2];
#pragma unroll
  for (int m = 0; m < 4; ++m) { acc[m][0] = 0ull; acc[m][1] = 0ull; }

  float4 av = *(const float4*)(arow + lk);
  float4 bv = *(const float4*)(brow + lk);
  As[0][lk + 0][lr] = av.x; As[0][lk + 1][lr] = av.y;
  As[0][lk + 2][lr] = av.z; As[0][lk + 3][lr] = av.w;
  Bs[0][lk + 0][lr] = bv.x; Bs[0][lk + 1][lr] = bv.y;
  Bs[0][lk + 2][lr] = bv.z; Bs[0][lk + 3][lr] = bv.w;
  __syncthreads();

  const int nChunks = kI / 16;  // 32
  for (int ci = 0; ci < nChunks; ++ci) {
    int cur = ci & 1;
    if (ci + 1 < nChunks) {
      int k0 = (ci + 1) * 16;
      av = *(const float4*)(arow + k0 + lk);
      bv = *(const float4*)(brow + k0 + lk);
    }
#pragma unroll
    for (int kk = 0; kk < 16; ++kk) {
      float4 a4 = *(const float4*)&As[cur][kk][ty * 4];
      unsigned long long b0 = *(const unsigned long long*)&Bs[cur][kk][tx * 4];
      unsigned long long b1 = *(const unsigned long long*)&Bs[cur][kk][tx * 4 + 2];
      unsigned long long a0 = pack2(a4.x, a4.x);
      unsigned long long a1 = pack2(a4.y, a4.y);
      unsigned long long a2 = pack2(a4.z, a4.z);
      unsigned long long a3 = pack2(a4.w, a4.w);
      fma2(acc[0][0], a0, b0); fma2(acc[0][1], a0, b1);
      fma2(acc[1][0], a1, b0); fma2(acc[1][1], a1, b1);
      fma2(acc[2][0], a2, b0); fma2(acc[2][1], a2, b1);
      fma2(acc[3][0], a3, b0); fma2(acc[3][1], a3, b1);
    }
    if (ci + 1 < nChunks) {
      int nxt = cur ^ 1;
      As[nxt][lk + 0][lr] = av.x; As[nxt][lk + 1][lr] = av.y;
      As[nxt][lk + 2][lr] = av.z; As[nxt][lk + 3][lr] = av.w;
      Bs[nxt][lk + 0][lr] = bv.x; Bs[nxt][lk + 1][lr] = bv.y;
      Bs[nxt][lk + 2][lr] = bv.z; Bs[nxt][lk + 3][lr] = bv.w;
    }
    __syncthreads();
  }

  const float* __restrict__ bptr = bias + (size_t)t * kH + colBase + tx * 4;
  float4 b4 = *(const float4*)bptr;
#pragma unroll
  for (int m = 0; m < 4; ++m) {
    int row = rowBase + ty * 4 + m;
    float2 lo = unpack2(acc[m][0]);
    float2 hi = unpack2(acc[m][1]);
    float4 o;
    o.x = lo.x + b4.x; o.y = lo.y + b4.y; o.z = hi.x + b4.z; o.w = hi.y + b4.w;
    *(float4*)(g_pre + ((size_t)t * kB + row) * kH + colBase + tx * 4) = o;
  }
}

// ---------------------------------------------------------------------------
// Phase B step t (serial): rows pos < c_t: h_out = tanh(pre[t][pos] + h_in[pos] @ Wh_t^T)
// Tile 16x64 over (pos, n). 256 threads = 2 K-groups of 128 (K=512 each).
// NEW: prefetch step t+1's Wh slab + pre tile into L2 (persists across launches).
__global__ __launch_bounds__(256) void step_kernel(int t, const float* __restrict__ Wh) {
  __shared__ float As[2][2][16][20];   // [grp][buf][k][m]
  __shared__ float Bs[2][2][16][68];   // [grp][buf][k][n]
  __shared__ float Red[16][68];

  const int c = g_count[t];
  const int rowBase = blockIdx.x * 16;
  if (rowBase >= c) return;
  const int colBase = blockIdx.y * 64;

  const int pp = t & 1;
  const float* __restrict__ hIn = g_h[pp];
  float* __restrict__ hOut = g_h[pp ^ 1];

  const int tid = threadIdx.x;
  const int g = tid >> 7;       // k-group 0/1
  const int ltid = tid & 127;
  const int kStart = g * 512;

  // loader indices
  const int lrA = ltid >> 3;          // 0..15 (row)
  const int lkA = (ltid & 7) * 2;     // k offset (float2)
  const int lnB = ltid >> 1;          // 0..63 (col)
  const int lkB = (ltid & 1) * 8;     // k offset (2x float4)

  const float* __restrict__ arow = hIn + (size_t)(rowBase + lrA) * kH + kStart;
  const float* __restrict__ brow =
      Wh + ((size_t)t * kH + colBase + lnB) * kH + kStart;

  // compute indices
  const int tx = ltid & 15;   // 4 cols
  const int ty = ltid >> 4;   // 0..7 -> 2 rows

  unsigned long long acc[2][2];
  acc[0][0] = acc[0][1] = acc[1][0] = acc[1][1] = 0ull;

  // preload chunk 0
  float2 av = *(const float2*)(arow + lkA);
  float4 bv0 = *(const float4*)(brow + lkB);
  float4 bv1 = *(const float4*)(brow + lkB + 4);
  As[g][0][lkA + 0][lrA] = av.x;
  As[g][0][lkA + 1][lrA] = av.y;
  Bs[g][0][lkB + 0][lnB] = bv0.x; Bs[g][0][lkB + 1][lnB] = bv0.y;
  Bs[g][0][lkB + 2][lnB] = bv0.z; Bs[g][0][lkB + 3][lnB] = bv0.w;
  Bs[g][0][lkB + 4][lnB] = bv1.x; Bs[g][0][lkB + 5][lnB] = bv1.y;
  Bs[g][0][lkB + 6][lnB] = bv1.z; Bs[g][0][lkB + 7][lnB] = bv1.w;

  // ---- L2 prefetch for step t+1 (deduplicated across the grid) ----
  if (t + 1 < kT) {
    if (blockIdx.x == 0) {
      // Wh_{t+1} slab for this col tile: 64 cols x 1024 k x 4B = 2048 lines
      const float* nf = Wh + ((size_t)(t + 1) * kH + colBase) * kH;
      for (int i = tid; i < 2048; i += 256) {
        int r = i >> 5;          // 0..63 (col within tile)
        int o = (i & 31) * 32;   // 128B line within the 4KB row
        pf_l2(nf + (size_t)r * kH + o);
      }
    }
    if (blockIdx.y == 0) {
      // pre[t+1] rows for this row tile: 16 rows x 1024 cols = 512 lines
      const float* pp2 = g_pre + ((size_t)(t + 1) * kB + rowBase) * kH;
      for (int i = tid; i < 512; i += 256) {
        int r = i >> 5;          // 0..15
        int o = (i & 31) * 32;
        pf_l2(pp2 + (size_t)r * kH + o);
      }
    }
  }
  __syncthreads();

  const int nChunks = 512 / 16;  // 32 per group
  for (int ci = 0; ci < nChunks; ++ci) {
    int cur = ci & 1;
    if (ci + 1 < nChunks) {
      int k0 = (ci + 1) * 16;
      av = *(const float2*)(arow + k0 + lkA);
      bv0 = *(const float4*)(brow + k0 + lkB);
      bv1 = *(const float4*)(brow + k0 + lkB + 4);
    }
#pragma unroll
    for (int kk = 0; kk < 16; ++kk) {
      float2 a2 = *(const float2*)&As[g][cur][kk][ty * 2];
      unsigned long long b0 = *(const unsigned long long*)&Bs[g][cur][kk][tx * 4];
      unsigned long long b1 = *(const unsigned long long*)&Bs[g][cur][kk][tx * 4 + 2];
      unsigned long long a0 = pack2(a2.x, a2.x);
      unsigned long long a1 = pack2(a2.y, a2.y);
      fma2(acc[0][0], a0, b0); fma2(acc[0][1], a0, b1);
      fma2(acc[1][0], a1, b0); fma2(acc[1][1], a1, b1);
    }
    if (ci + 1 < nChunks) {
      int nxt = cur ^ 1;
      As[g][nxt][lkA + 0][lrA] = av.x;
      As[g][nxt][lkA + 1][lrA] = av.y;
      Bs[g][nxt][lkB + 0][lnB] = bv0.x; Bs[g][nxt][lkB + 1][lnB] = bv0.y;
      Bs[g][nxt][lkB + 2][lnB] = bv0.z; Bs[g][nxt][lkB + 3][lnB] = bv0.w;
      Bs[g][nxt][lkB + 4][lnB] = bv1.x; Bs[g][nxt][lkB + 5][lnB] = bv1.y;
      Bs[g][nxt][lkB + 6][lnB] = bv1.z; Bs[g][nxt][lkB + 7][lnB] = bv1.w;
    }
    __syncthreads();
  }

  // group 1 deposits partials; group 0 reduces + epilogue
  if (g == 1) {
#pragma unroll
    for (int m = 0; m < 2; ++m) {
      *(unsigned long long*)&Red[ty * 2 + m][tx * 4 + 0] = acc[m][0];
      *(unsigned long long*)&Red[ty * 2 + m][tx * 4 + 2] = acc[m][1];
    }
  }
  __syncthreads();
  if (g == 0) {
#pragma unroll
    for (int m = 0; m < 2; ++m) {
      add2(acc[m][0], *(const unsigned long long*)&Red[ty * 2 + m][tx * 4 + 0]);
      add2(acc[m][1], *(const unsigned long long*)&Red[ty * 2 + m][tx * 4 + 2]);
      int pos = rowBase + ty * 2 + m;
      if (pos < c) {
        const float* pr = g_pre + ((size_t)t * kB + pos) * kH + colBase + tx * 4;
        float4 p4 = *(const float4*)pr;
        float2 lo = unpack2(acc[m][0]);
        float2 hi = unpack2(acc[m][1]);
        float4 o;
        o.x = tanhf(lo.x + p4.x);
        o.y = tanhf(lo.y + p4.y);
        o.z = tanhf(hi.x + p4.z);
        o.w = tanhf(hi.y + p4.w);
        *(float4*)(hOut + (size_t)pos * kH + colBase + tx * 4) = o;
      }
    }
  }
}

// ---------------------------------------------------------------------------
// out[order[pos]] = h_final[pos] . W_out + b_out  (final h lives in buffer L&1)
__global__ void out_kernel(const float* __restrict__ Wout,
                           const float* __restrict__ bout,
                           float* __restrict__ out) {
  int pos = blockIdx.x;
  int L = g_lens[pos];
  const float* h = g_h[L & 1] + (size_t)pos * kH;
  float s = 0.0f;
  for (int i = threadIdx.x; i < kH; i += blockDim.x) s += h[i] * Wout[i];
#pragma unroll
  for (int o = 16; o > 0; o >>= 1) s += __shfl_down_sync(0xffffffffu, s, o);
  __shared__ float red[4];
  if ((threadIdx.x & 31) == 0) red[threadIdx.x >> 5] = s;
  __syncthreads();
  if (threadIdx.x == 0) {
    float tot = red[0] + red[1] + red[2] + red[3];
    out[g_order[pos]] = tot + bout[0];
  }
}

// ---------------------------------------------------------------------------
extern "C" void kernel_launch(void* const* d_in, const int* in_sizes, int n_in,
                              void* d_out, int out_size) {
  const float* x = (const float*)d_in[0];
  const void* seq = d_in[1];
  const float* Wx = (const float*)d_in[2];
  const float* Wh = (const float*)d_in[3];
  const float* bias = (const float*)d_in[4];
  const float* Wout = (const float*)d_in[5];
  const float* bout = (const float*)d_in[6];
  float* out = (float*)d_out;

  init_kernel<<<(kB * kH + 255) / 256, 256>>>();
  sort_kernel<<<1, kB>>>(seq);

  // Phase A: all (t, row-tile, col-tile) GEMMs in one launch
  preA_kernel<<<dim3(kB / 64, kH / 64, kT), 256>>>(x, Wx, bias);

  // Phase B: sequential recurrence, L2-prefetching one step ahead
  for (int t = 0; t < kT; ++t) {
    step_kernel<<<dim3(16, 16), 256>>>(t, Wh);
  }
  out_kernel<<<kB, 128>>>(Wout, bout, out);
}